// round 4
// baseline (speedup 1.0000x reference)
#include <cuda_runtime.h>
#include <cuda_fp16.h>
#include <cstdint>

#define N_NODES 20000
#define N_EDGES 160000
#define DIM 32
#define EFD 95
#define EH 64
#define NG 64
#define ZCOLS 2048      // EH * DIM
#define BN_EPS 1e-5f

// ---------------- scratch (device globals) ----------------
__device__ float  g_h[(size_t)N_EDGES * EH];                    // 41 MB (src-sorted order)
__device__ __align__(16) __half g_Zh[(size_t)N_NODES * ZCOLS];  // 82 MB  [n][kb][o][r]
__device__ float  g_Zb[N_NODES * DIM];
__device__ float  g_agg[N_NODES * DIM];
__device__ float  g_x1[N_NODES * DIM];
__device__ float  g_pool[NG * DIM];

// sorting scratch
__device__ int g_cnt[N_NODES];
__device__ int g_cur[N_NODES];
__device__ int g_start[N_NODES + 1];
__device__ int g_rank[N_EDGES];      // edge e -> sorted position
__device__ int g_sdst[N_EDGES];      // dst in sorted order

// ---------------- zero kernels ----------------
__global__ void k_zero_agg() {
    int i = blockIdx.x * blockDim.x + threadIdx.x;
    if (i < N_NODES * DIM) g_agg[i] = 0.f;
}
__global__ void k_zero_pool_cnt() {
    int i = blockIdx.x * blockDim.x + threadIdx.x;
    if (i < NG * DIM) g_pool[i] = 0.f;
    if (i < N_NODES) g_cnt[i] = 0;
}

// ---------------- sort: histogram / scan / bin-fill ----------------
__global__ void k_hist(const int* __restrict__ src) {
    int e = blockIdx.x * blockDim.x + threadIdx.x;
    if (e < N_EDGES) atomicAdd(&g_cnt[src[e]], 1);
}

#define SCAN_T 1024
#define SCAN_C 20        // 1024*20 >= 20000
__global__ void k_scan() {
    __shared__ int part[SCAN_T];
    int t = threadIdx.x;
    int base = t * SCAN_C;
    int loc[SCAN_C];
    int sum = 0;
#pragma unroll
    for (int j = 0; j < SCAN_C; j++) {
        int idx = base + j;
        int v = (idx < N_NODES) ? g_cnt[idx] : 0;
        loc[j] = sum;
        sum += v;
    }
    part[t] = sum;
    __syncthreads();
    for (int off = 1; off < SCAN_T; off <<= 1) {
        int v = (t >= off) ? part[t - off] : 0;
        __syncthreads();
        part[t] += v;
        __syncthreads();
    }
    int excl = part[t] - sum;
#pragma unroll
    for (int j = 0; j < SCAN_C; j++) {
        int idx = base + j;
        if (idx < N_NODES) {
            int st = excl + loc[j];
            g_start[idx] = st;
            g_cur[idx] = st;
        }
    }
    if (t == SCAN_T - 1) g_start[N_NODES] = part[SCAN_T - 1];
}

__global__ void k_binfill(const int* __restrict__ src, const int* __restrict__ dst) {
    int e = blockIdx.x * blockDim.x + threadIdx.x;
    if (e >= N_EDGES) return;
    int s = src[e];
    int pos = atomicAdd(&g_cur[s], 1);
    g_rank[e] = pos;
    g_sdst[pos] = dst[e];
}

// ---------------- K1: edge MLP -> writes h at sorted position ----------------
__global__ void k_edge_mlp(const float* __restrict__ ea,
                           const float* __restrict__ W1,
                           const float* __restrict__ b1) {
    __shared__ float W1s[EFD * EH];
    __shared__ float eas[16 * EFD];
    __shared__ float b1s[EH];
    int t = threadIdx.x;
    for (int i = t; i < EFD * EH; i += 256) W1s[i] = W1[i];
    if (t < EH) b1s[t] = b1[t];
    int e0 = blockIdx.x * 16;
    for (int i = t; i < 16 * EFD; i += 256) eas[i] = ea[(size_t)e0 * EFD + i];
    __syncthreads();

    int tx = t & 15, ty = t >> 4;
    int e = e0 + ty;
    float4 acc = make_float4(b1s[tx * 4 + 0], b1s[tx * 4 + 1],
                             b1s[tx * 4 + 2], b1s[tx * 4 + 3]);
    const float* ear = &eas[ty * EFD];
#pragma unroll 5
    for (int k = 0; k < EFD; k++) {
        float a = ear[k];
        float4 w = *(const float4*)&W1s[k * EH + tx * 4];
        acc.x = fmaf(a, w.x, acc.x);
        acc.y = fmaf(a, w.y, acc.y);
        acc.z = fmaf(a, w.z, acc.z);
        acc.w = fmaf(a, w.w, acc.w);
    }
    float4 r = make_float4(fmaxf(acc.x, 0.f), fmaxf(acc.y, 0.f),
                           fmaxf(acc.z, 0.f), fmaxf(acc.w, 0.f));
    int row = g_rank[e];
    *(float4*)&g_h[(size_t)row * EH + tx * 4] = r;
}

// ---------------- K2: Zh[n][kb][o][r] = sum_i X[n,i] * W2[(kb*8+r)*1024 + i*32 + o] --
__global__ void __launch_bounds__(256) k_zgemm(const float* __restrict__ X,
                                               const float* __restrict__ W2) {
    __shared__ float Xs[32 * DIM];
    __shared__ float Bs[8 * 32 * 32];
    int t = threadIdx.x;
    int kb = blockIdx.x;
    int n0 = blockIdx.y * 32;

    for (int i = t; i < 32 * DIM; i += 256)
        Xs[i] = X[(size_t)n0 * DIM + i];
    const float* w2src = W2 + (size_t)kb * 8192;
#pragma unroll
    for (int i = 0; i < 8192; i += 256)
        Bs[i + t] = w2src[i + t];
    __syncthreads();

    int o = t & 31, trow = t >> 5;
    float acc[4][8] = {};
#pragma unroll
    for (int i = 0; i < DIM; i++) {
        float b[8];
#pragma unroll
        for (int r = 0; r < 8; r++) b[r] = Bs[r * 1024 + i * 32 + o];
#pragma unroll
        for (int rr = 0; rr < 4; rr++) {
            float a = Xs[(trow * 4 + rr) * DIM + i];
#pragma unroll
            for (int r = 0; r < 8; r++)
                acc[rr][r] = fmaf(a, b[r], acc[rr][r]);
        }
    }
#pragma unroll
    for (int rr = 0; rr < 4; rr++) {
        int n = n0 + trow * 4 + rr;
        __half2 p0 = __floats2half2_rn(acc[rr][0], acc[rr][1]);
        __half2 p1 = __floats2half2_rn(acc[rr][2], acc[rr][3]);
        __half2 p2 = __floats2half2_rn(acc[rr][4], acc[rr][5]);
        __half2 p3 = __floats2half2_rn(acc[rr][6], acc[rr][7]);
        uint4 pk = make_uint4(*(uint32_t*)&p0, *(uint32_t*)&p1,
                              *(uint32_t*)&p2, *(uint32_t*)&p3);
        *(uint4*)&g_Zh[(size_t)n * ZCOLS + kb * 256 + o * 8] = pk;
    }
}

// ---------------- K2b: Zb[n,o] = sum_i X[n,i] * b2[i*32+o] ----------------
__global__ void k_zb(const float* __restrict__ X, const float* __restrict__ b2) {
    __shared__ float Bs[DIM * DIM];
    int t = threadIdx.x;
    for (int i = t; i < DIM * DIM; i += 256) Bs[i] = b2[i];
    __syncthreads();
    int n = blockIdx.x * 8 + (t >> 5);
    int o = t & 31;
    const float* xr = X + (size_t)n * DIM;
    float v = 0.f;
#pragma unroll
    for (int i = 0; i < DIM; i++) v = fmaf(xr[i], Bs[i * DIM + o], v);
    g_Zb[n * DIM + o] = v;
}

// ---------------- K3: grouped scatter — warp per src node ----------------
// Z row loaded to registers once; per edge: stage h row (sorted, linear),
// 64 FMA per lane, atomicAdd to dst.
__global__ void __launch_bounds__(256) k_scatter2() {
    __shared__ float hs[8][EH];
    int gwarp = (blockIdx.x * 256 + threadIdx.x) >> 5;
    if (gwarp >= N_NODES) return;
    int lane = threadIdx.x & 31;
    int wloc = (threadIdx.x >> 5);
    int s = gwarp;
    int beg = g_start[s], end = g_start[s + 1];
    if (beg == end) return;

    // load Z row for this node: lane o = lane, all 64 k values -> floats
    float zf[EH];
    const __half* zr = g_Zh + (size_t)s * ZCOLS + lane * 8;
#pragma unroll
    for (int kb = 0; kb < 8; kb++) {
        uint4 v = *(const uint4*)(zr + kb * 256);
        float2 p0 = __half22float2(*(__half2*)&v.x);
        float2 p1 = __half22float2(*(__half2*)&v.y);
        float2 p2 = __half22float2(*(__half2*)&v.z);
        float2 p3 = __half22float2(*(__half2*)&v.w);
        zf[kb * 8 + 0] = p0.x; zf[kb * 8 + 1] = p0.y;
        zf[kb * 8 + 2] = p1.x; zf[kb * 8 + 3] = p1.y;
        zf[kb * 8 + 4] = p2.x; zf[kb * 8 + 5] = p2.y;
        zf[kb * 8 + 6] = p3.x; zf[kb * 8 + 7] = p3.y;
    }
    float zb = g_Zb[s * DIM + lane];
    float* hw = hs[wloc];

    for (int i = beg; i < end; i++) {
        if (lane < 16)
            *(float4*)&hw[lane * 4] = *(const float4*)&g_h[(size_t)i * EH + lane * 4];
        __syncwarp();
        float msg = zb;
#pragma unroll
        for (int k = 0; k < EH; k += 4) {
            float4 h4 = *(const float4*)&hw[k];
            msg = fmaf(h4.x, zf[k + 0], msg);
            msg = fmaf(h4.y, zf[k + 1], msg);
            msg = fmaf(h4.z, zf[k + 2], msg);
            msg = fmaf(h4.w, zf[k + 3], msg);
        }
        int d = g_sdst[i];
        atomicAdd(&g_agg[d * DIM + lane], msg);
        __syncwarp();
    }
}

// ---------------- K4: node update ----------------
template <bool POOL>
__global__ void k_node_update(const float* __restrict__ xin,
                              const float* __restrict__ root,
                              const float* __restrict__ bias,
                              const float* __restrict__ bng,
                              const float* __restrict__ bnb,
                              const float* __restrict__ bnrm,
                              const float* __restrict__ bnrv,
                              float* __restrict__ xout,
                              const int* __restrict__ batch) {
    __shared__ float Rs[DIM * DIM];
    int t = threadIdx.x;
    for (int i = t; i < DIM * DIM; i += 256) Rs[i] = root[i];
    __syncthreads();
    int n = blockIdx.x * 8 + (t >> 5);
    int o = t & 31;
    const float* xr = xin + (size_t)n * DIM;
    float v = g_agg[n * DIM + o] + bias[o];
#pragma unroll
    for (int i = 0; i < DIM; i++) v = fmaf(xr[i], Rs[i * DIM + o], v);
    v = (v - bnrm[o]) * rsqrtf(bnrv[o] + BN_EPS) * bng[o] + bnb[o];
    v = fmaxf(v, 0.f);
    if (POOL) {
        int b = batch[n];
        atomicMax((int*)&g_pool[b * DIM + o], __float_as_int(v));
    } else {
        xout[n * DIM + o] = v;
    }
}

// ---------------- K6: head ----------------
__global__ void k_head(const float* __restrict__ l1W, const float* __restrict__ l1b,
                       const float* __restrict__ l2W, const float* __restrict__ l2b,
                       float* __restrict__ out) {
    int g = threadIdx.x;
    const float* pr = &g_pool[g * DIM];
    float tbuf[DIM];
#pragma unroll
    for (int j = 0; j < DIM; j++) {
        float v = l1b[j];
#pragma unroll
        for (int i = 0; i < DIM; i++) v = fmaf(pr[i], l1W[i * DIM + j], v);
        tbuf[j] = fmaxf(v, 0.f);
    }
#pragma unroll
    for (int c = 0; c < 2; c++) {
        float v = l2b[c];
#pragma unroll
        for (int j = 0; j < DIM; j++) v = fmaf(tbuf[j], l2W[j * 2 + c], v);
        out[g * 2 + c] = v;
    }
}

// ---------------- launch ----------------
extern "C" void kernel_launch(void* const* d_in, const int* in_sizes, int n_in,
                              void* d_out, int out_size) {
    const float* x     = (const float*)d_in[0];
    const int*   esrc  = (const int*)d_in[1];
    const int*   edst  = (const int*)d_in[2];
    const float* ea    = (const float*)d_in[3];
    const int*   batch = (const int*)d_in[4];

    const float* c0W1 = (const float*)d_in[5];
    const float* c0b1 = (const float*)d_in[6];
    const float* c0W2 = (const float*)d_in[7];
    const float* c0b2 = (const float*)d_in[8];
    const float* c0rt = (const float*)d_in[9];
    const float* c0bs = (const float*)d_in[10];
    const float* bn0g = (const float*)d_in[11];
    const float* bn0b = (const float*)d_in[12];
    const float* bn0m = (const float*)d_in[13];
    const float* bn0v = (const float*)d_in[14];

    const float* c1W1 = (const float*)d_in[15];
    const float* c1b1 = (const float*)d_in[16];
    const float* c1W2 = (const float*)d_in[17];
    const float* c1b2 = (const float*)d_in[18];
    const float* c1rt = (const float*)d_in[19];
    const float* c1bs = (const float*)d_in[20];
    const float* bn1g = (const float*)d_in[21];
    const float* bn1b = (const float*)d_in[22];
    const float* bn1m = (const float*)d_in[23];
    const float* bn1v = (const float*)d_in[24];

    const float* l1W = (const float*)d_in[25];
    const float* l1b = (const float*)d_in[26];
    const float* l2W = (const float*)d_in[27];
    const float* l2b = (const float*)d_in[28];

    float* out = (float*)d_out;

    void* px1 = nullptr;
    cudaGetSymbolAddress(&px1, g_x1);
    float* x1 = (float*)px1;

    dim3 zg(8, N_NODES / 32);

    // ---- sort edges by src (once; shared by both convs) ----
    k_zero_pool_cnt<<<(N_NODES + 255) / 256, 256>>>();
    k_hist<<<(N_EDGES + 255) / 256, 256>>>(esrc);
    k_scan<<<1, SCAN_T>>>();
    k_binfill<<<(N_EDGES + 255) / 256, 256>>>(esrc, edst);

    // ---- conv0 ----
    k_zero_agg<<<(N_NODES * DIM + 255) / 256, 256>>>();
    k_edge_mlp<<<N_EDGES / 16, 256>>>(ea, c0W1, c0b1);
    k_zgemm<<<zg, 256>>>(x, c0W2);
    k_zb<<<N_NODES / 8, 256>>>(x, c0b2);
    k_scatter2<<<(N_NODES * 32 + 255) / 256, 256>>>();
    k_node_update<false><<<N_NODES / 8, 256>>>(x, c0rt, c0bs, bn0g, bn0b, bn0m, bn0v,
                                               x1, nullptr);

    // ---- conv1 ----
    k_zero_agg<<<(N_NODES * DIM + 255) / 256, 256>>>();
    k_edge_mlp<<<N_EDGES / 16, 256>>>(ea, c1W1, c1b1);
    k_zgemm<<<zg, 256>>>(x1, c1W2);
    k_zb<<<N_NODES / 8, 256>>>(x1, c1b2);
    k_scatter2<<<(N_NODES * 32 + 255) / 256, 256>>>();
    k_node_update<true><<<N_NODES / 8, 256>>>(x1, c1rt, c1bs, bn1g, bn1b, bn1m, bn1v,
                                              nullptr, batch);

    // ---- head ----
    k_head<<<1, NG>>>(l1W, l1b, l2W, l2b, out);
}

// round 5
// speedup vs baseline: 1.0891x; 1.0891x over previous
#include <cuda_runtime.h>
#include <cuda_fp16.h>
#include <cstdint>

#define N_NODES 20000
#define N_EDGES 160000
#define DIM 32
#define EFD 95
#define EH 64
#define NG 64
#define ZCOLS 2048      // EH * DIM
#define BN_EPS 1e-5f

// ---------------- scratch (device globals) ----------------
__device__ float  g_h[(size_t)N_EDGES * EH];                    // 41 MB (src-sorted order)
__device__ __align__(16) __half g_Zh[(size_t)N_NODES * ZCOLS];  // 82 MB  [n][kb][o][r]
__device__ float  g_Zb[N_NODES * DIM];
__device__ float  g_agg[N_NODES * DIM];
__device__ float  g_x1[N_NODES * DIM];
__device__ float  g_pool[NG * DIM];

// sorting scratch
__device__ int g_cnt[N_NODES];
__device__ int g_cur[N_NODES];
__device__ int g_start[N_NODES + 1];
__device__ int g_rank[N_EDGES];      // edge e -> sorted position
__device__ int g_ssrc[N_EDGES];      // src in sorted order
__device__ int g_sdst[N_EDGES];      // dst in sorted order

// ---------------- zero kernels ----------------
__global__ void k_zero_agg() {
    int i = blockIdx.x * blockDim.x + threadIdx.x;
    if (i < N_NODES * DIM) g_agg[i] = 0.f;
}
__global__ void k_zero_pool_cnt() {
    int i = blockIdx.x * blockDim.x + threadIdx.x;
    if (i < NG * DIM) g_pool[i] = 0.f;
    if (i < N_NODES) g_cnt[i] = 0;
}

// ---------------- sort: histogram / scan / bin-fill ----------------
__global__ void k_hist(const int* __restrict__ src) {
    int e = blockIdx.x * blockDim.x + threadIdx.x;
    if (e < N_EDGES) atomicAdd(&g_cnt[src[e]], 1);
}

#define SCAN_T 1024
#define SCAN_C 20        // 1024*20 >= 20000
__global__ void k_scan() {
    __shared__ int part[SCAN_T];
    int t = threadIdx.x;
    int base = t * SCAN_C;
    int loc[SCAN_C];
    int sum = 0;
#pragma unroll
    for (int j = 0; j < SCAN_C; j++) {
        int idx = base + j;
        int v = (idx < N_NODES) ? g_cnt[idx] : 0;
        loc[j] = sum;
        sum += v;
    }
    part[t] = sum;
    __syncthreads();
    for (int off = 1; off < SCAN_T; off <<= 1) {
        int v = (t >= off) ? part[t - off] : 0;
        __syncthreads();
        part[t] += v;
        __syncthreads();
    }
    int excl = part[t] - sum;
#pragma unroll
    for (int j = 0; j < SCAN_C; j++) {
        int idx = base + j;
        if (idx < N_NODES) {
            int st = excl + loc[j];
            g_start[idx] = st;
            g_cur[idx] = st;
        }
    }
    if (t == SCAN_T - 1) g_start[N_NODES] = part[SCAN_T - 1];
}

__global__ void k_binfill(const int* __restrict__ src, const int* __restrict__ dst) {
    int e = blockIdx.x * blockDim.x + threadIdx.x;
    if (e >= N_EDGES) return;
    int s = src[e];
    int pos = atomicAdd(&g_cur[s], 1);
    g_rank[e] = pos;
    g_ssrc[pos] = s;
    g_sdst[pos] = dst[e];
}

// ---------------- K1: edge MLP -> writes h at sorted position ----------------
__global__ void k_edge_mlp(const float* __restrict__ ea,
                           const float* __restrict__ W1,
                           const float* __restrict__ b1) {
    __shared__ float W1s[EFD * EH];
    __shared__ float eas[16 * EFD];
    __shared__ float b1s[EH];
    int t = threadIdx.x;
    for (int i = t; i < EFD * EH; i += 256) W1s[i] = W1[i];
    if (t < EH) b1s[t] = b1[t];
    int e0 = blockIdx.x * 16;
    for (int i = t; i < 16 * EFD; i += 256) eas[i] = ea[(size_t)e0 * EFD + i];
    __syncthreads();

    int tx = t & 15, ty = t >> 4;
    int e = e0 + ty;
    float4 acc = make_float4(b1s[tx * 4 + 0], b1s[tx * 4 + 1],
                             b1s[tx * 4 + 2], b1s[tx * 4 + 3]);
    const float* ear = &eas[ty * EFD];
#pragma unroll 5
    for (int k = 0; k < EFD; k++) {
        float a = ear[k];
        float4 w = *(const float4*)&W1s[k * EH + tx * 4];
        acc.x = fmaf(a, w.x, acc.x);
        acc.y = fmaf(a, w.y, acc.y);
        acc.z = fmaf(a, w.z, acc.z);
        acc.w = fmaf(a, w.w, acc.w);
    }
    float4 r = make_float4(fmaxf(acc.x, 0.f), fmaxf(acc.y, 0.f),
                           fmaxf(acc.z, 0.f), fmaxf(acc.w, 0.f));
    int row = g_rank[e];
    *(float4*)&g_h[(size_t)row * EH + tx * 4] = r;
}

// ---------------- K2: Zh[n][kb][o][r] = sum_i X[n,i] * W2[(kb*8+r)*1024 + i*32 + o] --
__global__ void __launch_bounds__(256) k_zgemm(const float* __restrict__ X,
                                               const float* __restrict__ W2) {
    __shared__ float Xs[32 * DIM];
    __shared__ float Bs[8 * 32 * 32];
    int t = threadIdx.x;
    int kb = blockIdx.x;
    int n0 = blockIdx.y * 32;

    for (int i = t; i < 32 * DIM; i += 256)
        Xs[i] = X[(size_t)n0 * DIM + i];
    const float* w2src = W2 + (size_t)kb * 8192;
#pragma unroll
    for (int i = 0; i < 8192; i += 256)
        Bs[i + t] = w2src[i + t];
    __syncthreads();

    int o = t & 31, trow = t >> 5;
    float acc[4][8] = {};
#pragma unroll
    for (int i = 0; i < DIM; i++) {
        float b[8];
#pragma unroll
        for (int r = 0; r < 8; r++) b[r] = Bs[r * 1024 + i * 32 + o];
#pragma unroll
        for (int rr = 0; rr < 4; rr++) {
            float a = Xs[(trow * 4 + rr) * DIM + i];
#pragma unroll
            for (int r = 0; r < 8; r++)
                acc[rr][r] = fmaf(a, b[r], acc[rr][r]);
        }
    }
#pragma unroll
    for (int rr = 0; rr < 4; rr++) {
        int n = n0 + trow * 4 + rr;
        __half2 p0 = __floats2half2_rn(acc[rr][0], acc[rr][1]);
        __half2 p1 = __floats2half2_rn(acc[rr][2], acc[rr][3]);
        __half2 p2 = __floats2half2_rn(acc[rr][4], acc[rr][5]);
        __half2 p3 = __floats2half2_rn(acc[rr][6], acc[rr][7]);
        uint4 pk = make_uint4(*(uint32_t*)&p0, *(uint32_t*)&p1,
                              *(uint32_t*)&p2, *(uint32_t*)&p3);
        *(uint4*)&g_Zh[(size_t)n * ZCOLS + kb * 256 + o * 8] = pk;
    }
}

// ---------------- K2b: Zb[n,o] = sum_i X[n,i] * b2[i*32+o] ----------------
__global__ void k_zb(const float* __restrict__ X, const float* __restrict__ b2) {
    __shared__ float Bs[DIM * DIM];
    int t = threadIdx.x;
    for (int i = t; i < DIM * DIM; i += 256) Bs[i] = b2[i];
    __syncthreads();
    int n = blockIdx.x * 8 + (t >> 5);
    int o = t & 31;
    const float* xr = X + (size_t)n * DIM;
    float v = 0.f;
#pragma unroll
    for (int i = 0; i < DIM; i++) v = fmaf(xr[i], Bs[i * DIM + o], v);
    g_Zb[n * DIM + o] = v;
}

// ---------------- K3: scatter over SORTED edges — warp per edge ----------------
// Consecutive warps share src node -> Z row reused from L1/L2.
// msg[o] = Zb[s,o] + sum_kb sum_r h_sorted[i, kb*8+r] * Zh[s][kb][o][r]
__global__ void __launch_bounds__(256) k_scatter3() {
    __shared__ float hsh[8 * EH];       // 8 sorted edges/block, linear h rows
    int t = threadIdx.x;
    size_t hbase = (size_t)blockIdx.x * (8 * EH);
    hsh[t] = g_h[hbase + t];
    hsh[t + 256] = g_h[hbase + t + 256];
    __syncthreads();

    int wid = t >> 5, lane = t & 31;
    int i = blockIdx.x * 8 + wid;
    int s = g_ssrc[i], d = g_sdst[i];
    const __half* zr = g_Zh + (size_t)s * ZCOLS + lane * 8;
    const float* hr = &hsh[wid * EH];
    float msg0 = g_Zb[s * DIM + lane];
    float msg1 = 0.f;
#pragma unroll
    for (int kb = 0; kb < 8; kb += 2) {
        uint4 v0 = __ldg((const uint4*)(zr + kb * 256));
        uint4 v1 = __ldg((const uint4*)(zr + (kb + 1) * 256));
        float2 a0 = __half22float2(*(__half2*)&v0.x);
        float2 a1 = __half22float2(*(__half2*)&v0.y);
        float2 a2 = __half22float2(*(__half2*)&v0.z);
        float2 a3 = __half22float2(*(__half2*)&v0.w);
        float2 b0 = __half22float2(*(__half2*)&v1.x);
        float2 b1 = __half22float2(*(__half2*)&v1.y);
        float2 b2 = __half22float2(*(__half2*)&v1.z);
        float2 b3 = __half22float2(*(__half2*)&v1.w);
        const float* h0 = hr + kb * 8;
        msg0 = fmaf(h0[0], a0.x, msg0);
        msg1 = fmaf(h0[1], a0.y, msg1);
        msg0 = fmaf(h0[2], a1.x, msg0);
        msg1 = fmaf(h0[3], a1.y, msg1);
        msg0 = fmaf(h0[4], a2.x, msg0);
        msg1 = fmaf(h0[5], a2.y, msg1);
        msg0 = fmaf(h0[6], a3.x, msg0);
        msg1 = fmaf(h0[7], a3.y, msg1);
        const float* h1 = hr + kb * 8 + 8;
        msg0 = fmaf(h1[0], b0.x, msg0);
        msg1 = fmaf(h1[1], b0.y, msg1);
        msg0 = fmaf(h1[2], b1.x, msg0);
        msg1 = fmaf(h1[3], b1.y, msg1);
        msg0 = fmaf(h1[4], b2.x, msg0);
        msg1 = fmaf(h1[5], b2.y, msg1);
        msg0 = fmaf(h1[6], b3.x, msg0);
        msg1 = fmaf(h1[7], b3.y, msg1);
    }
    atomicAdd(&g_agg[d * DIM + lane], msg0 + msg1);
}

// ---------------- K4: node update ----------------
template <bool POOL>
__global__ void k_node_update(const float* __restrict__ xin,
                              const float* __restrict__ root,
                              const float* __restrict__ bias,
                              const float* __restrict__ bng,
                              const float* __restrict__ bnb,
                              const float* __restrict__ bnrm,
                              const float* __restrict__ bnrv,
                              float* __restrict__ xout,
                              const int* __restrict__ batch) {
    __shared__ float Rs[DIM * DIM];
    int t = threadIdx.x;
    for (int i = t; i < DIM * DIM; i += 256) Rs[i] = root[i];
    __syncthreads();
    int n = blockIdx.x * 8 + (t >> 5);
    int o = t & 31;
    const float* xr = xin + (size_t)n * DIM;
    float v = g_agg[n * DIM + o] + bias[o];
#pragma unroll
    for (int i = 0; i < DIM; i++) v = fmaf(xr[i], Rs[i * DIM + o], v);
    v = (v - bnrm[o]) * rsqrtf(bnrv[o] + BN_EPS) * bng[o] + bnb[o];
    v = fmaxf(v, 0.f);
    if (POOL) {
        int b = batch[n];
        atomicMax((int*)&g_pool[b * DIM + o], __float_as_int(v));
    } else {
        xout[n * DIM + o] = v;
    }
}

// ---------------- K6: head ----------------
__global__ void k_head(const float* __restrict__ l1W, const float* __restrict__ l1b,
                       const float* __restrict__ l2W, const float* __restrict__ l2b,
                       float* __restrict__ out) {
    int g = threadIdx.x;
    const float* pr = &g_pool[g * DIM];
    float tbuf[DIM];
#pragma unroll
    for (int j = 0; j < DIM; j++) {
        float v = l1b[j];
#pragma unroll
        for (int i = 0; i < DIM; i++) v = fmaf(pr[i], l1W[i * DIM + j], v);
        tbuf[j] = fmaxf(v, 0.f);
    }
#pragma unroll
    for (int c = 0; c < 2; c++) {
        float v = l2b[c];
#pragma unroll
        for (int j = 0; j < DIM; j++) v = fmaf(tbuf[j], l2W[j * 2 + c], v);
        out[g * 2 + c] = v;
    }
}

// ---------------- launch ----------------
extern "C" void kernel_launch(void* const* d_in, const int* in_sizes, int n_in,
                              void* d_out, int out_size) {
    const float* x     = (const float*)d_in[0];
    const int*   esrc  = (const int*)d_in[1];
    const int*   edst  = (const int*)d_in[2];
    const float* ea    = (const float*)d_in[3];
    const int*   batch = (const int*)d_in[4];

    const float* c0W1 = (const float*)d_in[5];
    const float* c0b1 = (const float*)d_in[6];
    const float* c0W2 = (const float*)d_in[7];
    const float* c0b2 = (const float*)d_in[8];
    const float* c0rt = (const float*)d_in[9];
    const float* c0bs = (const float*)d_in[10];
    const float* bn0g = (const float*)d_in[11];
    const float* bn0b = (const float*)d_in[12];
    const float* bn0m = (const float*)d_in[13];
    const float* bn0v = (const float*)d_in[14];

    const float* c1W1 = (const float*)d_in[15];
    const float* c1b1 = (const float*)d_in[16];
    const float* c1W2 = (const float*)d_in[17];
    const float* c1b2 = (const float*)d_in[18];
    const float* c1rt = (const float*)d_in[19];
    const float* c1bs = (const float*)d_in[20];
    const float* bn1g = (const float*)d_in[21];
    const float* bn1b = (const float*)d_in[22];
    const float* bn1m = (const float*)d_in[23];
    const float* bn1v = (const float*)d_in[24];

    const float* l1W = (const float*)d_in[25];
    const float* l1b = (const float*)d_in[26];
    const float* l2W = (const float*)d_in[27];
    const float* l2b = (const float*)d_in[28];

    float* out = (float*)d_out;

    void* px1 = nullptr;
    cudaGetSymbolAddress(&px1, g_x1);
    float* x1 = (float*)px1;

    dim3 zg(8, N_NODES / 32);

    // ---- sort edges by src (once; shared by both convs) ----
    k_zero_pool_cnt<<<(N_NODES + 255) / 256, 256>>>();
    k_hist<<<(N_EDGES + 255) / 256, 256>>>(esrc);
    k_scan<<<1, SCAN_T>>>();
    k_binfill<<<(N_EDGES + 255) / 256, 256>>>(esrc, edst);

    // ---- conv0 ----
    k_zero_agg<<<(N_NODES * DIM + 255) / 256, 256>>>();
    k_edge_mlp<<<N_EDGES / 16, 256>>>(ea, c0W1, c0b1);
    k_zgemm<<<zg, 256>>>(x, c0W2);
    k_zb<<<N_NODES / 8, 256>>>(x, c0b2);
    k_scatter3<<<N_EDGES / 8, 256>>>();
    k_node_update<false><<<N_NODES / 8, 256>>>(x, c0rt, c0bs, bn0g, bn0b, bn0m, bn0v,
                                               x1, nullptr);

    // ---- conv1 ----
    k_zero_agg<<<(N_NODES * DIM + 255) / 256, 256>>>();
    k_edge_mlp<<<N_EDGES / 16, 256>>>(ea, c1W1, c1b1);
    k_zgemm<<<zg, 256>>>(x1, c1W2);
    k_zb<<<N_NODES / 8, 256>>>(x1, c1b2);
    k_scatter3<<<N_EDGES / 8, 256>>>();
    k_node_update<true><<<N_NODES / 8, 256>>>(x1, c1rt, c1bs, bn1g, bn1b, bn1m, bn1v,
                                              nullptr, batch);

    // ---- head ----
    k_head<<<1, NG>>>(l1W, l1b, l2W, l2b, out);
}